// round 13
// baseline (speedup 1.0000x reference)
#include <cuda_runtime.h>
#include <cstddef>

typedef unsigned long long u64;

// biases / eps only in constant (low LDC count)
__constant__ float cB0[64], cB1[64];
__constant__ float cF1b[16], cF2b[16];
__constant__ float cDB[64];
__constant__ float cEps[4];

__device__ __forceinline__ u64 pk(float lo, float hi) {
    u64 r; asm("mov.b64 %0,{%1,%2};" : "=l"(r) : "f"(lo), "f"(hi)); return r;
}
__device__ __forceinline__ void upk(u64 p, float& a, float& b) {
    asm("mov.b64 {%0,%1},%2;" : "=f"(a), "=f"(b) : "l"(p));
}
__device__ __forceinline__ u64 fma2(u64 a, u64 b, u64 c) {
    u64 d; asm("fma.rn.f32x2 %0,%1,%2,%3;" : "=l"(d) : "l"(a), "l"(b), "l"(c)); return d;
}
__device__ __forceinline__ u64 mul2(u64 a, u64 b) {
    u64 d; asm("mul.rn.f32x2 %0,%1,%2;" : "=l"(d) : "l"(a), "l"(b)); return d;
}
__device__ __forceinline__ u64 add2(u64 a, u64 b) {
    u64 d; asm("add.rn.f32x2 %0,%1,%2;" : "=l"(d) : "l"(a), "l"(b)); return d;
}

// ONE weight-row load (4 warp-uniform LDG.128, L1-hot), TWO dot products (A,B)
__device__ __forceinline__ void dot2(const float* __restrict__ w,
                                     const u64* vA, const u64* vB,
                                     float& oA, float& oB) {
    const ulonglong2* w2 = (const ulonglong2*)w;
    ulonglong2 p0 = w2[0], p1 = w2[1], p2 = w2[2], p3 = w2[3];
    u64 a0 = mul2(p0.x, vA[0]);
    u64 a1 = mul2(p0.y, vA[1]);
    a0 = fma2(p1.x, vA[2], a0);  a1 = fma2(p1.y, vA[3], a1);
    a0 = fma2(p2.x, vA[4], a0);  a1 = fma2(p2.y, vA[5], a1);
    a0 = fma2(p3.x, vA[6], a0);  a1 = fma2(p3.y, vA[7], a1);
    u64 b0 = mul2(p0.x, vB[0]);
    u64 b1 = mul2(p0.y, vB[1]);
    b0 = fma2(p1.x, vB[2], b0);  b1 = fma2(p1.y, vB[3], b1);
    b0 = fma2(p2.x, vB[4], b0);  b1 = fma2(p2.y, vB[5], b1);
    b0 = fma2(p3.x, vB[6], b0);  b1 = fma2(p3.y, vB[7], b1);
    a0 = add2(a0, a1);  b0 = add2(b0, b1);
    float xa, ya, xb, yb; upk(a0, xa, ya); upk(b0, xb, yb);
    oA = xa + ya;  oB = xb + yb;
}

// smem (floats): BN tables [0,208); per-warp scratch 3536 at 208 + w*3536
// scratch: [0,1352) adjTA, [1352,2704) adjTB, [2704,3120) xbA, [3120,3536) xbB
// (decoder: [0,676) reused as rb).  Total = 208 + 2*3536 = 7280 fl = 29.1 KB static.
__global__ __launch_bounds__(64, 6) void gvae_kernel(
    const float* __restrict__ adj,
    const float* __restrict__ init_w,    // [13,16]   (global, L1-hot)
    const float* __restrict__ w0g, const float* __restrict__ w1g,
    const float* __restrict__ dwg,       // [4,16,16] (global, L1-hot)
    const float* __restrict__ fc1w, const float* __restrict__ fc2w,
    const float* __restrict__ big, const float* __restrict__ bib,
    const float* __restrict__ bim, const float* __restrict__ biv,
    const float* __restrict__ bog, const float* __restrict__ bob,
    const float* __restrict__ bom, const float* __restrict__ bov,
    float* __restrict__ out, int B)
{
    __shared__ __align__(16) float smem[208 + 2 * 3536];
    float* sSin = smem;        float* sTin  = smem + 52;
    float* sSout = smem + 104; float* sTout = smem + 156;

    const int tid = threadIdx.x;
    for (int t = tid; t < 52; t += 64) {
        float si = big[t] * rsqrtf(biv[t] + 1e-5f);
        sSin[t]  = si; sTin[t]  = bib[t] - bim[t] * si;
        float so = bog[t] * rsqrtf(bov[t] + 1e-5f);
        sSout[t] = so; sTout[t] = bob[t] - bom[t] * so;
    }
    __syncthreads();

    const int w    = tid >> 5;             // 2 warps per block
    const int lane = tid & 31;
    const int sub  = lane >> 4;
    const int n    = lane & 15;
    const int nn   = (n < 13) ? n : 12;
    const bool act = (n < 13);
    const long b0  = (long)blockIdx.x * 8 + (long)w * 4;   // 4 graphs per warp
    if (b0 >= B) return;
    const long gA = b0 + sub, gB = b0 + sub + 2;

    const size_t muOff = (size_t)B * 676;
    const size_t lvOff = muOff + (size_t)B * 208;
    float* ws  = smem + 208 + w * 3536;
    float* xbA = ws + 2704;
    float* xbB = ws + 3120;

    // ---- stage 4 graphs' adj coalesced ----
    {
        const float4* g  = (const float4*)(adj + (size_t)b0 * 676);
        float4*       s4 = (float4*)ws;
        for (int t = lane; t < 676; t += 32) s4[t] = g[t];
    }
    __syncwarp();

    float r[4][13];
    u64 xpA[8], xpB[8];

    // ---- phase 1: graphs B (raw upper half), compute xB, write adjTB ----
#pragma unroll
    for (int c = 0; c < 4; c++)
#pragma unroll
        for (int m = 0; m < 13; m++)
            r[c][m] = ws[(sub + 2) * 676 + c * 169 + nn * 13 + m];
    {
        float a = r[0][0] + r[1][0] + r[2][0] + r[3][0];
        u64 am = pk(a, a);
        const ulonglong2* wm = (const ulonglong2*)init_w;
        ulonglong2 p0 = wm[0], p1 = wm[1], p2 = wm[2], p3 = wm[3];
        xpB[0] = mul2(am, p0.x); xpB[1] = mul2(am, p0.y);
        xpB[2] = mul2(am, p1.x); xpB[3] = mul2(am, p1.y);
        xpB[4] = mul2(am, p2.x); xpB[5] = mul2(am, p2.y);
        xpB[6] = mul2(am, p3.x); xpB[7] = mul2(am, p3.y);
#pragma unroll
        for (int m = 1; m < 13; m++) {
            float am1 = r[0][m] + r[1][m] + r[2][m] + r[3][m];
            u64 a2 = pk(am1, am1);
            const ulonglong2* wv = (const ulonglong2*)(init_w + m * 16);
            ulonglong2 q0 = wv[0], q1 = wv[1], q2 = wv[2], q3 = wv[3];
            xpB[0] = fma2(a2, q0.x, xpB[0]); xpB[1] = fma2(a2, q0.y, xpB[1]);
            xpB[2] = fma2(a2, q1.x, xpB[2]); xpB[3] = fma2(a2, q1.y, xpB[3]);
            xpB[4] = fma2(a2, q2.x, xpB[4]); xpB[5] = fma2(a2, q2.y, xpB[5]);
            xpB[6] = fma2(a2, q3.x, xpB[6]); xpB[7] = fma2(a2, q3.y, xpB[7]);
        }
    }
    __syncwarp();
    if (act) {
        float4* aT = (float4*)ws;
#pragma unroll
        for (int m = 0; m < 13; m++) {
            float4 v; v.x = r[0][m]; v.y = r[1][m]; v.z = r[2][m]; v.w = r[3][m];
            aT[338 + m * 26 + sub * 13 + nn] = v;
        }
    }
    __syncwarp();

    // ---- phase 2: graphs A (raw lower half), compute xA, write adjTA ----
#pragma unroll
    for (int c = 0; c < 4; c++)
#pragma unroll
        for (int m = 0; m < 13; m++)
            r[c][m] = ws[sub * 676 + c * 169 + nn * 13 + m];
    {
        float a = r[0][0] + r[1][0] + r[2][0] + r[3][0];
        u64 am = pk(a, a);
        const ulonglong2* wm = (const ulonglong2*)init_w;
        ulonglong2 p0 = wm[0], p1 = wm[1], p2 = wm[2], p3 = wm[3];
        xpA[0] = mul2(am, p0.x); xpA[1] = mul2(am, p0.y);
        xpA[2] = mul2(am, p1.x); xpA[3] = mul2(am, p1.y);
        xpA[4] = mul2(am, p2.x); xpA[5] = mul2(am, p2.y);
        xpA[6] = mul2(am, p3.x); xpA[7] = mul2(am, p3.y);
#pragma unroll
        for (int m = 1; m < 13; m++) {
            float am1 = r[0][m] + r[1][m] + r[2][m] + r[3][m];
            u64 a2 = pk(am1, am1);
            const ulonglong2* wv = (const ulonglong2*)(init_w + m * 16);
            ulonglong2 q0 = wv[0], q1 = wv[1], q2 = wv[2], q3 = wv[3];
            xpA[0] = fma2(a2, q0.x, xpA[0]); xpA[1] = fma2(a2, q0.y, xpA[1]);
            xpA[2] = fma2(a2, q1.x, xpA[2]); xpA[3] = fma2(a2, q1.y, xpA[3]);
            xpA[4] = fma2(a2, q2.x, xpA[4]); xpA[5] = fma2(a2, q2.y, xpA[5]);
            xpA[6] = fma2(a2, q3.x, xpA[6]); xpA[7] = fma2(a2, q3.y, xpA[7]);
        }
    }
    __syncwarp();
    if (act) {
        float4* aT = (float4*)ws;
#pragma unroll
        for (int m = 0; m < 13; m++) {
            float4 v; v.x = r[0][m]; v.y = r[1][m]; v.z = r[2][m]; v.w = r[3][m];
            aT[m * 26 + sub * 13 + nn] = v;
        }
    }
    __syncwarp();

    // ---- 4 GIN layers ----
    const float4* aTA = (const float4*)ws;
    const float4* aTB = aTA + 338;
    for (int l = 0; l < 4; l++) {
        if (act) {
            ulonglong2* xa = (ulonglong2*)(xbA + (sub * 13 + nn) * 16);
            ulonglong2* xv = (ulonglong2*)(xbB + (sub * 13 + nn) * 16);
#pragma unroll
            for (int q = 0; q < 4; q++) {
                ulonglong2 va; va.x = xpA[2*q]; va.y = xpA[2*q+1]; xa[q] = va;
                ulonglong2 vb; vb.x = xpB[2*q]; vb.y = xpB[2*q+1]; xv[q] = vb;
            }
        }
        __syncwarp();

        const float ep = 1.0f + cEps[l];
        const u64 ep2 = pk(ep, ep);
        u64 agA[8], agB[8];
#pragma unroll
        for (int q = 0; q < 8; q++) { agA[q] = mul2(ep2, xpA[q]); agB[q] = mul2(ep2, xpB[q]); }
#pragma unroll
        for (int m = 0; m < 13; m++) {
            float4 aA = aTA[m * 26 + sub * 13 + nn];
            const ulonglong2* xv = (const ulonglong2*)(xbA + (sub * 13 + m) * 16);
            ulonglong2 v0 = xv[0], v1 = xv[1], v2 = xv[2], v3 = xv[3];
            u64 c0 = pk(aA.x, aA.x), c1 = pk(aA.y, aA.y);
            u64 c2 = pk(aA.z, aA.z), c3 = pk(aA.w, aA.w);
            agA[0] = fma2(c0, v0.x, agA[0]); agA[1] = fma2(c0, v0.y, agA[1]);
            agA[2] = fma2(c1, v1.x, agA[2]); agA[3] = fma2(c1, v1.y, agA[3]);
            agA[4] = fma2(c2, v2.x, agA[4]); agA[5] = fma2(c2, v2.y, agA[5]);
            agA[6] = fma2(c3, v3.x, agA[6]); agA[7] = fma2(c3, v3.y, agA[7]);
            float4 aB = aTB[m * 26 + sub * 13 + nn];
            const ulonglong2* yv = (const ulonglong2*)(xbB + (sub * 13 + m) * 16);
            ulonglong2 u0 = yv[0], u1 = yv[1], u2 = yv[2], u3 = yv[3];
            u64 d0 = pk(aB.x, aB.x), d1 = pk(aB.y, aB.y);
            u64 d2 = pk(aB.z, aB.z), d3 = pk(aB.w, aB.w);
            agB[0] = fma2(d0, u0.x, agB[0]); agB[1] = fma2(d0, u0.y, agB[1]);
            agB[2] = fma2(d1, u1.x, agB[2]); agB[3] = fma2(d1, u1.y, agB[3]);
            agB[4] = fma2(d2, u2.x, agB[4]); agB[5] = fma2(d2, u2.y, agB[5]);
            agB[6] = fma2(d3, u3.x, agB[6]); agB[7] = fma2(d3, u3.y, agB[7]);
        }
        __syncwarp();

        const float sin_  = sSin[l*13 + nn],  tin_  = sTin[l*13 + nn];
        const float sout_ = sSout[l*13 + nn], tout_ = sTout[l*13 + nn];
        u64 hA[8], hB[8];
#pragma unroll
        for (int q = 0; q < 8; q++) {
            float a0A, a0B, a1A, a1B;
            dot2(w0g + l*256 + (2*q)*16,   agA, agB, a0A, a0B);
            dot2(w0g + l*256 + (2*q+1)*16, agA, agB, a1A, a1B);
            float b0c = cB0[l*16 + 2*q], b1c = cB0[l*16 + 2*q + 1];
            float v0A = fmaf(sin_, a0A + b0c, tin_), v1A = fmaf(sin_, a1A + b1c, tin_);
            float v0B = fmaf(sin_, a0B + b0c, tin_), v1B = fmaf(sin_, a1B + b1c, tin_);
            hA[q] = pk(fmaxf(v0A, 0.01f*v0A), fmaxf(v1A, 0.01f*v1A));
            hB[q] = pk(fmaxf(v0B, 0.01f*v0B), fmaxf(v1B, 0.01f*v1B));
        }
#pragma unroll
        for (int q = 0; q < 8; q++) {
            float a0A, a0B, a1A, a1B;
            dot2(w1g + l*256 + (2*q)*16,   hA, hB, a0A, a0B);
            dot2(w1g + l*256 + (2*q+1)*16, hA, hB, a1A, a1B);
            float b0c = cB1[l*16 + 2*q], b1c = cB1[l*16 + 2*q + 1];
            float v0A = fmaf(sout_, a0A + b0c, tout_), v1A = fmaf(sout_, a1A + b1c, tout_);
            float v0B = fmaf(sout_, a0B + b0c, tout_), v1B = fmaf(sout_, a1B + b1c, tout_);
            xpA[q] = pk(fmaxf(v0A, 0.01f*v0A), fmaxf(v1A, 0.01f*v1A));
            xpB[q] = pk(fmaxf(v0B, 0.01f*v0B), fmaxf(v1B, 0.01f*v1B));
        }
    }

    // ---- fc1 -> mu (=z), fc2 -> logvar ----
    u64 zA[8], zB[8];
#pragma unroll
    for (int q = 0; q < 8; q++) {
        float a0A, a0B, a1A, a1B;
        dot2(fc1w + (2*q)*16,   xpA, xpB, a0A, a0B);
        dot2(fc1w + (2*q+1)*16, xpA, xpB, a1A, a1B);
        float b0c = cF1b[2*q], b1c = cF1b[2*q+1];
        zA[q] = pk(a0A + b0c, a1A + b1c);
        zB[q] = pk(a0B + b0c, a1B + b1c);
    }
    {
        float lvA[16], lvB[16];
#pragma unroll
        for (int q = 0; q < 8; q++) {
            float a0A, a0B, a1A, a1B;
            dot2(fc2w + (2*q)*16,   xpA, xpB, a0A, a0B);
            dot2(fc2w + (2*q+1)*16, xpA, xpB, a1A, a1B);
            lvA[2*q] = a0A + cF2b[2*q]; lvA[2*q+1] = a1A + cF2b[2*q+1];
            lvB[2*q] = a0B + cF2b[2*q]; lvB[2*q+1] = a1B + cF2b[2*q+1];
        }
        if (act) {
            ulonglong2* oA = (ulonglong2*)(out + muOff + ((size_t)gA * 13 + n) * 16);
            ulonglong2* oB = (ulonglong2*)(out + muOff + ((size_t)gB * 13 + n) * 16);
#pragma unroll
            for (int q = 0; q < 4; q++) {
                ulonglong2 va; va.x = zA[2*q]; va.y = zA[2*q+1]; oA[q] = va;
                ulonglong2 vb; vb.x = zB[2*q]; vb.y = zB[2*q+1]; oB[q] = vb;
            }
            float4* lA = (float4*)(out + lvOff + ((size_t)gA * 13 + n) * 16);
            float4* lB = (float4*)(out + lvOff + ((size_t)gB * 13 + n) * 16);
#pragma unroll
            for (int q = 0; q < 4; q++) {
                float4 va; va.x = lvA[4*q]; va.y = lvA[4*q+1]; va.z = lvA[4*q+2]; va.w = lvA[4*q+3];
                lA[q] = va;
                float4 vb; vb.x = lvB[4*q]; vb.y = lvB[4*q+1]; vb.z = lvB[4*q+2]; vb.w = lvB[4*q+3];
                lB[q] = vb;
            }
        }
    }

    // ---- decoder: recon = relu(T T^T); adjT dead -> rb = ws[0,676) ----
    float* rb = ws;
    for (int k = 0; k < 4; k++) {
        u64 tA[8], tB[8];
#pragma unroll
        for (int q = 0; q < 8; q++) {
            float a0A, a0B, a1A, a1B;
            dot2(dwg + k*256 + (2*q)*16,   zA, zB, a0A, a0B);
            dot2(dwg + k*256 + (2*q+1)*16, zA, zB, a1A, a1B);
            float b0c = cDB[k*16 + 2*q], b1c = cDB[k*16 + 2*q + 1];
            tA[q] = pk(a0A + b0c, a1A + b1c);
            tB[q] = pk(a0B + b0c, a1B + b1c);
        }
        __syncwarp();
        if (act) {
            ulonglong2* xa = (ulonglong2*)(xbA + (sub * 13 + nn) * 16);
            ulonglong2* xv = (ulonglong2*)(xbB + (sub * 13 + nn) * 16);
#pragma unroll
            for (int q = 0; q < 4; q++) {
                ulonglong2 va; va.x = tA[2*q]; va.y = tA[2*q+1]; xa[q] = va;
                ulonglong2 vb; vb.x = tB[2*q]; vb.y = tB[2*q+1]; xv[q] = vb;
            }
        }
        __syncwarp();

#pragma unroll
        for (int m = 0; m < 13; m++) {
            const ulonglong2* xv = (const ulonglong2*)(xbA + (sub * 13 + m) * 16);
            ulonglong2 v0 = xv[0], v1 = xv[1], v2 = xv[2], v3 = xv[3];
            u64 s0 = mul2(tA[0], v0.x);
            u64 s1 = mul2(tA[1], v0.y);
            s0 = fma2(tA[2], v1.x, s0); s1 = fma2(tA[3], v1.y, s1);
            s0 = fma2(tA[4], v2.x, s0); s1 = fma2(tA[5], v2.y, s1);
            s0 = fma2(tA[6], v3.x, s0); s1 = fma2(tA[7], v3.y, s1);
            s0 = add2(s0, s1);
            float x0, x1; upk(s0, x0, x1);
            float rA = fmaxf(x0 + x1, 0.0f);
            const ulonglong2* yv = (const ulonglong2*)(xbB + (sub * 13 + m) * 16);
            ulonglong2 u0 = yv[0], u1 = yv[1], u2 = yv[2], u3 = yv[3];
            u64 t0 = mul2(tB[0], u0.x);
            u64 t1 = mul2(tB[1], u0.y);
            t0 = fma2(tB[2], u1.x, t0); t1 = fma2(tB[3], u1.y, t1);
            t0 = fma2(tB[4], u2.x, t0); t1 = fma2(tB[5], u2.y, t1);
            t0 = fma2(tB[6], u3.x, t0); t1 = fma2(tB[7], u3.y, t1);
            t0 = add2(t0, t1);
            float y0, y1; upk(t0, y0, y1);
            float rB = fmaxf(y0 + y1, 0.0f);
            if (act) {
                rb[sub * 169 + nn * 13 + m]       = rA;
                rb[(sub + 2) * 169 + nn * 13 + m] = rB;
            }
        }
        __syncwarp();
#pragma unroll
        for (int g = 0; g < 4; g++) {
            float* og = out + ((size_t)(b0 + g) * 4 + k) * 169;
            for (int t = lane; t < 169; t += 32) og[t] = rb[g * 169 + t];
        }
        __syncwarp();
    }
}

extern "C" void kernel_launch(void* const* d_in, const int* in_sizes, int n_in,
                              void* d_out, int out_size) {
    cudaMemcpyToSymbolAsync(cEps, d_in[2],   4 * 4, 0, cudaMemcpyDeviceToDevice);
    cudaMemcpyToSymbolAsync(cB0,  d_in[4],  64 * 4, 0, cudaMemcpyDeviceToDevice);
    cudaMemcpyToSymbolAsync(cB1,  d_in[6],  64 * 4, 0, cudaMemcpyDeviceToDevice);
    cudaMemcpyToSymbolAsync(cF1b, d_in[16], 16 * 4, 0, cudaMemcpyDeviceToDevice);
    cudaMemcpyToSymbolAsync(cF2b, d_in[18], 16 * 4, 0, cudaMemcpyDeviceToDevice);
    cudaMemcpyToSymbolAsync(cDB,  d_in[20], 64 * 4, 0, cudaMemcpyDeviceToDevice);

    const float* adj = (const float*)d_in[0];
    float* out = (float*)d_out;
    int B = in_sizes[0] / 676;
    int grid = (B + 7) / 8;                // 8 graphs per 64-thread block
    gvae_kernel<<<grid, 64>>>(adj,
        (const float*)d_in[1],
        (const float*)d_in[3],  (const float*)d_in[5],  (const float*)d_in[19],
        (const float*)d_in[15], (const float*)d_in[17],
        (const float*)d_in[7],  (const float*)d_in[8],
        (const float*)d_in[9],  (const float*)d_in[10],
        (const float*)d_in[11], (const float*)d_in[12],
        (const float*)d_in[13], (const float*)d_in[14],
        out, B);
}

// round 14
// speedup vs baseline: 1.0916x; 1.0916x over previous
#include <cuda_runtime.h>
#include <cstddef>

typedef unsigned long long u64;

// ---- scalar/bias parameters in constant (low traffic) ----
__constant__ float cB0[64], cB1[64];
__constant__ float cF1b[16], cF2b[16];
__constant__ float cDB[64];
__constant__ float cEps[4];

// ---- packed f32x2 primitives ----
__device__ __forceinline__ u64 pk(float lo, float hi) {
    u64 r; asm("mov.b64 %0,{%1,%2};" : "=l"(r) : "f"(lo), "f"(hi)); return r;
}
__device__ __forceinline__ void upk(u64 p, float& a, float& b) {
    asm("mov.b64 {%0,%1},%2;" : "=f"(a), "=f"(b) : "l"(p));
}
__device__ __forceinline__ u64 fma2(u64 a, u64 b, u64 c) {
    u64 d; asm("fma.rn.f32x2 %0,%1,%2,%3;" : "=l"(d) : "l"(a), "l"(b), "l"(c)); return d;
}
__device__ __forceinline__ u64 mul2(u64 a, u64 b) {
    u64 d; asm("mul.rn.f32x2 %0,%1,%2;" : "=l"(d) : "l"(a), "l"(b)); return d;
}
__device__ __forceinline__ u64 add2(u64 a, u64 b) {
    u64 d; asm("add.rn.f32x2 %0,%1,%2;" : "=l"(d) : "l"(a), "l"(b)); return d;
}

// dot: 16-float smem row (16B aligned, LDS.128) with packed 8xf32x2 vector
__device__ __forceinline__ float dot16s(const float* __restrict__ w, const u64* v) {
    const ulonglong2* w2 = (const ulonglong2*)w;
    ulonglong2 p0 = w2[0], p1 = w2[1], p2 = w2[2], p3 = w2[3];
    u64 a0 = mul2(p0.x, v[0]);
    u64 a1 = mul2(p0.y, v[1]);
    a0 = fma2(p1.x, v[2], a0);
    a1 = fma2(p1.y, v[3], a1);
    a0 = fma2(p2.x, v[4], a0);
    a1 = fma2(p2.y, v[5], a1);
    a0 = fma2(p3.x, v[6], a0);
    a1 = fma2(p3.y, v[7], a1);
    a0 = add2(a0, a1);
    float x, y; upk(a0, x, y);
    return x + y;
}

__global__ __launch_bounds__(128, 5) void gvae_kernel(
    const float* __restrict__ adj,       // [B,4,13,13]
    const float* __restrict__ init_w,    // [13,16]
    const float* __restrict__ w0g, const float* __restrict__ w1g,
    const float* __restrict__ dwg,       // [4,16,16] each
    const float* __restrict__ fc1w, const float* __restrict__ fc2w, // [16,16]
    const float* __restrict__ big, const float* __restrict__ bib,
    const float* __restrict__ bim, const float* __restrict__ biv,
    const float* __restrict__ bog, const float* __restrict__ bob,
    const float* __restrict__ bom, const float* __restrict__ bov,
    float* __restrict__ out, int B)
{
    __shared__ __align__(16) float sW0[1024], sW1[1024], sDW[1024];  // 12 KB
    __shared__ __align__(16) float sWi[208];                         // init_weight
    __shared__ __align__(16) float sF1[256], sF2[256];               // fc1/fc2
    __shared__ float sSin[52], sTin[52], sSout[52], sTout[52];       // folded BN
    __shared__ __align__(16) float scr[4 * 1352];                    // raw adj / adjT / rb
    __shared__ __align__(16) float xbs[4 * 416];                     // x broadcast

    const int tid = threadIdx.x;
    for (int t = tid; t < 1024; t += 128) { sW0[t] = w0g[t]; sW1[t] = w1g[t]; sDW[t] = dwg[t]; }
    for (int t = tid; t < 208;  t += 128) sWi[t] = init_w[t];
    for (int t = tid; t < 256;  t += 128) { sF1[t] = fc1w[t]; sF2[t] = fc2w[t]; }
    for (int t = tid; t < 52; t += 128) {
        float si = big[t] * rsqrtf(biv[t] + 1e-5f);
        sSin[t]  = si; sTin[t]  = bib[t] - bim[t] * si;
        float so = bog[t] * rsqrtf(bov[t] + 1e-5f);
        sSout[t] = so; sTout[t] = bob[t] - bom[t] * so;
    }
    __syncthreads();

    const int w    = tid >> 5;
    const int lane = tid & 31;
    const int sub  = lane >> 4;            // 2 graphs per warp
    const int n    = lane & 15;            // node id; active if n < 13
    const int nn   = (n < 13) ? n : 12;
    const bool act = (n < 13);
    const long b0  = (long)blockIdx.x * 8 + (long)w * 2;
    if (b0 >= B) return;

    const size_t muOff = (size_t)B * 676;
    const size_t lvOff = muOff + (size_t)B * 208;
    float* scw = scr + w * 1352;           // raw adj -> adjT -> rb
    float* xb  = xbs + w * 416;            // [2][13][16] broadcast

    // ---- stage raw adj via cp.async (no register round-trip, no STS) ----
    {
        const float4* g = (const float4*)(adj + (size_t)b0 * 676);
        unsigned smem_dst = (unsigned)__cvta_generic_to_shared(scw);
        for (int t = lane; t < 338; t += 32) {
            asm volatile("cp.async.ca.shared.global [%0], [%1], 16;"
                         :: "r"(smem_dst + t * 16), "l"(g + t));
        }
        asm volatile("cp.async.commit_group;");
        asm volatile("cp.async.wait_group 0;" ::: "memory");
    }
    __syncwarp();

    // ---- read this lane's rows (transient regs), compute xp, write adjT ----
    float raw[4][13];
#pragma unroll
    for (int c = 0; c < 4; c++)
#pragma unroll
        for (int m = 0; m < 13; m++)
            raw[c][m] = scw[sub * 676 + c * 169 + nn * 13 + m];

    u64 xp[8];
    {
        float a0 = raw[0][0] + raw[1][0] + raw[2][0] + raw[3][0];
        u64 aa = pk(a0, a0);
        const ulonglong2* wm = (const ulonglong2*)sWi;
        ulonglong2 q0 = wm[0], q1 = wm[1], q2 = wm[2], q3 = wm[3];
        xp[0] = mul2(aa, q0.x); xp[1] = mul2(aa, q0.y);
        xp[2] = mul2(aa, q1.x); xp[3] = mul2(aa, q1.y);
        xp[4] = mul2(aa, q2.x); xp[5] = mul2(aa, q2.y);
        xp[6] = mul2(aa, q3.x); xp[7] = mul2(aa, q3.y);
#pragma unroll
        for (int m = 1; m < 13; m++) {
            float a = raw[0][m] + raw[1][m] + raw[2][m] + raw[3][m];
            u64 am = pk(a, a);
            const ulonglong2* wv = (const ulonglong2*)(sWi + m * 16);
            ulonglong2 p0 = wv[0], p1 = wv[1], p2 = wv[2], p3 = wv[3];
            xp[0] = fma2(am, p0.x, xp[0]); xp[1] = fma2(am, p0.y, xp[1]);
            xp[2] = fma2(am, p1.x, xp[2]); xp[3] = fma2(am, p1.y, xp[3]);
            xp[4] = fma2(am, p2.x, xp[4]); xp[5] = fma2(am, p2.y, xp[5]);
            xp[6] = fma2(am, p3.x, xp[6]); xp[7] = fma2(am, p3.y, xp[7]);
        }
    }
    __syncwarp();          // all raw reads done before adjT overwrites
    // adjT layout: float4 slot = m*26 + sub*13 + nn  (lane-consecutive, conflict-free)
    if (act) {
        float4* adjT = (float4*)scw;
#pragma unroll
        for (int m = 0; m < 13; m++) {
            float4 v; v.x = raw[0][m]; v.y = raw[1][m]; v.z = raw[2][m]; v.w = raw[3][m];
            adjT[m * 26 + sub * 13 + nn] = v;
        }
    }
    __syncwarp();

    // ---- 4 GIN layers ----
    const float4* adjT = (const float4*)scw;
    for (int l = 0; l < 4; l++) {
        if (act) {
            ulonglong2* xv = (ulonglong2*)(xb + (sub * 13 + nn) * 16);
#pragma unroll
            for (int q = 0; q < 4; q++) {
                ulonglong2 v; v.x = xp[2*q]; v.y = xp[2*q+1];
                xv[q] = v;
            }
        }
        __syncwarp();

        const float ep = 1.0f + cEps[l];
        const u64 ep2 = pk(ep, ep);
        u64 agg[8];
#pragma unroll
        for (int q = 0; q < 8; q++) agg[q] = mul2(ep2, xp[q]);
#pragma unroll
        for (int m = 0; m < 13; m++) {
            float4 a4 = adjT[m * 26 + sub * 13 + nn];
            const ulonglong2* xv = (const ulonglong2*)(xb + (sub * 13 + m) * 16);
            ulonglong2 v0 = xv[0], v1 = xv[1], v2 = xv[2], v3 = xv[3];
            u64 a0 = pk(a4.x, a4.x);
            u64 a1 = pk(a4.y, a4.y);
            u64 a2 = pk(a4.z, a4.z);
            u64 a3 = pk(a4.w, a4.w);
            agg[0] = fma2(a0, v0.x, agg[0]); agg[1] = fma2(a0, v0.y, agg[1]);
            agg[2] = fma2(a1, v1.x, agg[2]); agg[3] = fma2(a1, v1.y, agg[3]);
            agg[4] = fma2(a2, v2.x, agg[4]); agg[5] = fma2(a2, v2.y, agg[5]);
            agg[6] = fma2(a3, v3.x, agg[6]); agg[7] = fma2(a3, v3.y, agg[7]);
        }
        __syncwarp();      // xb free for next writer

        const float sin_  = sSin[l*13 + nn],  tin_  = sTin[l*13 + nn];
        const float sout_ = sSout[l*13 + nn], tout_ = sTout[l*13 + nn];
        u64 hp[8];
#pragma unroll
        for (int q = 0; q < 8; q++) {
            float acc0 = cB0[l*16 + 2*q]     + dot16s(sW0 + l*256 + (2*q)*16,   agg);
            float acc1 = cB0[l*16 + 2*q + 1] + dot16s(sW0 + l*256 + (2*q+1)*16, agg);
            float v0 = fmaf(sin_, acc0, tin_);
            float v1 = fmaf(sin_, acc1, tin_);
            hp[q] = pk(fmaxf(v0, 0.01f * v0), fmaxf(v1, 0.01f * v1));
        }
#pragma unroll
        for (int q = 0; q < 8; q++) {
            float acc0 = cB1[l*16 + 2*q]     + dot16s(sW1 + l*256 + (2*q)*16,   hp);
            float acc1 = cB1[l*16 + 2*q + 1] + dot16s(sW1 + l*256 + (2*q+1)*16, hp);
            float v0 = fmaf(sout_, acc0, tout_);
            float v1 = fmaf(sout_, acc1, tout_);
            xp[q] = pk(fmaxf(v0, 0.01f * v0), fmaxf(v1, 0.01f * v1));
        }
    }

    // ---- fc1 -> mu (=z), fc2 -> logvar ----
    u64 zp[8];
#pragma unroll
    for (int q = 0; q < 8; q++) {
        float z0 = cF1b[2*q]     + dot16s(sF1 + (2*q)*16,   xp);
        float z1 = cF1b[2*q + 1] + dot16s(sF1 + (2*q+1)*16, xp);
        zp[q] = pk(z0, z1);
    }
    if (act) {
        ulonglong2* o = (ulonglong2*)(out + muOff + ((size_t)(b0 + sub) * 13 + n) * 16);
#pragma unroll
        for (int q = 0; q < 4; q++) {
            ulonglong2 v; v.x = zp[2*q]; v.y = zp[2*q+1];
            o[q] = v;
        }
        ulonglong2* o2 = (ulonglong2*)(out + lvOff + ((size_t)(b0 + sub) * 13 + n) * 16);
#pragma unroll
        for (int q = 0; q < 4; q++) {
            ulonglong2 v;
            v.x = pk(cF2b[4*q]   + dot16s(sF2 + (4*q)*16,   xp),
                     cF2b[4*q+1] + dot16s(sF2 + (4*q+1)*16, xp));
            v.y = pk(cF2b[4*q+2] + dot16s(sF2 + (4*q+2)*16, xp),
                     cF2b[4*q+3] + dot16s(sF2 + (4*q+3)*16, xp));
            o2[q] = v;
        }
    }

    // ---- decoder: per channel k, recon = relu(T T^T); adjT dead -> rb = scw ----
    float* rb = scw;
    for (int k = 0; k < 4; k++) {
        u64 tp2[8];
#pragma unroll
        for (int q = 0; q < 8; q++) {
            float t0 = cDB[k*16 + 2*q]     + dot16s(sDW + k*256 + (2*q)*16,   zp);
            float t1 = cDB[k*16 + 2*q + 1] + dot16s(sDW + k*256 + (2*q+1)*16, zp);
            tp2[q] = pk(t0, t1);
        }

        __syncwarp();      // prior readers of xb / rb done
        if (act) {
            ulonglong2* tv = (ulonglong2*)(xb + (sub * 13 + nn) * 16);
#pragma unroll
            for (int q = 0; q < 4; q++) {
                ulonglong2 v; v.x = tp2[2*q]; v.y = tp2[2*q+1];
                tv[q] = v;
            }
        }
        __syncwarp();

        float r[13];
#pragma unroll
        for (int m = 0; m < 13; m++) {
            const ulonglong2* tv = (const ulonglong2*)(xb + (sub * 13 + m) * 16);
            ulonglong2 v0 = tv[0], v1 = tv[1], v2 = tv[2], v3 = tv[3];
            u64 s0 = mul2(tp2[0], v0.x);
            u64 s1 = mul2(tp2[1], v0.y);
            s0 = fma2(tp2[2], v1.x, s0);
            s1 = fma2(tp2[3], v1.y, s1);
            s0 = fma2(tp2[4], v2.x, s0);
            s1 = fma2(tp2[5], v2.y, s1);
            s0 = fma2(tp2[6], v3.x, s0);
            s1 = fma2(tp2[7], v3.y, s1);
            s0 = add2(s0, s1);
            float x0, x1; upk(s0, x0, x1);
            r[m] = fmaxf(x0 + x1, 0.0f);
        }
        if (act) {
#pragma unroll
            for (int m = 0; m < 13; m++) rb[sub * 169 + nn * 13 + m] = r[m];
        }
        __syncwarp();
        // coalesced store of both graphs' 169-float recon rows
        for (int t = lane; t < 338; t += 32) {
            int s2 = (t >= 169) ? 1 : 0;
            int rr = t - 169 * s2;
            out[((size_t)(b0 + s2) * 4 + k) * 169 + rr] = rb[t];
        }
        __syncwarp();
    }
}

extern "C" void kernel_launch(void* const* d_in, const int* in_sizes, int n_in,
                              void* d_out, int out_size) {
    cudaMemcpyToSymbolAsync(cEps, d_in[2],   4 * 4, 0, cudaMemcpyDeviceToDevice);
    cudaMemcpyToSymbolAsync(cB0,  d_in[4],  64 * 4, 0, cudaMemcpyDeviceToDevice);
    cudaMemcpyToSymbolAsync(cB1,  d_in[6],  64 * 4, 0, cudaMemcpyDeviceToDevice);
    cudaMemcpyToSymbolAsync(cF1b, d_in[16], 16 * 4, 0, cudaMemcpyDeviceToDevice);
    cudaMemcpyToSymbolAsync(cF2b, d_in[18], 16 * 4, 0, cudaMemcpyDeviceToDevice);
    cudaMemcpyToSymbolAsync(cDB,  d_in[20], 64 * 4, 0, cudaMemcpyDeviceToDevice);

    const float* adj = (const float*)d_in[0];
    float* out = (float*)d_out;
    int B = in_sizes[0] / 676;
    int grid = (B + 7) / 8;                // 8 graphs per 128-thread block
    gvae_kernel<<<grid, 128>>>(adj,
        (const float*)d_in[1],
        (const float*)d_in[3],  (const float*)d_in[5],  (const float*)d_in[19],
        (const float*)d_in[15], (const float*)d_in[17],
        (const float*)d_in[7],  (const float*)d_in[8],
        (const float*)d_in[9],  (const float*)d_in[10],
        (const float*)d_in[11], (const float*)d_in[12],
        (const float*)d_in[13], (const float*)d_in[14],
        out, B);
}